// round 15
// baseline (speedup 1.0000x reference)
#include <cuda_runtime.h>
#include <cuda_fp16.h>
#include <cstdint>

#define KK 4096
#define NN 11008
#define MM 4096

// scratch: x in fp16 only (W is dequantized inside the GEMM now)
__device__ __half g_A[(size_t)MM * KK];   // [M, K]

// ---------------------------------------------------------------------------
// helpers
// ---------------------------------------------------------------------------
__device__ __forceinline__ uint32_t smem_u32(const void* p) {
    uint32_t a;
    asm("{ .reg .u64 t; cvta.to.shared.u64 t, %1; cvt.u32.u64 %0, t; }"
        : "=r"(a) : "l"(p));
    return a;
}
__device__ __forceinline__ void cp16(uint32_t s, const void* g) {
    asm volatile("cp.async.cg.shared.global [%0], [%1], 16;" :: "r"(s), "l"(g));
}
__device__ __forceinline__ void ldsm4(uint32_t& r0, uint32_t& r1, uint32_t& r2,
                                      uint32_t& r3, uint32_t a) {
    asm volatile("ldmatrix.sync.aligned.m8n8.x4.shared.b16 {%0,%1,%2,%3}, [%4];"
                 : "=r"(r0), "=r"(r1), "=r"(r2), "=r"(r3) : "r"(a));
}
__device__ __forceinline__ void ldsm4t(uint32_t& r0, uint32_t& r1, uint32_t& r2,
                                       uint32_t& r3, uint32_t a) {
    asm volatile("ldmatrix.sync.aligned.m8n8.x4.trans.shared.b16 {%0,%1,%2,%3}, [%4];"
                 : "=r"(r0), "=r"(r1), "=r"(r2), "=r"(r3) : "r"(a));
}
__device__ __forceinline__ void mma16816(float* d, const uint32_t* a,
                                         uint32_t b0, uint32_t b1) {
    asm volatile("mma.sync.aligned.m16n8k16.row.col.f32.f16.f16.f32 "
                 "{%0,%1,%2,%3}, {%4,%5,%6,%7}, {%8,%9}, {%0,%1,%2,%3};"
                 : "+f"(d[0]), "+f"(d[1]), "+f"(d[2]), "+f"(d[3])
                 : "r"(a[0]), "r"(a[1]), "r"(a[2]), "r"(a[3]), "r"(b0), "r"(b1));
}
__device__ __forceinline__ __half2 u2h(uint32_t u) {
    __half2 h; *reinterpret_cast<uint32_t*>(&h) = u; return h;
}
__device__ __forceinline__ uint32_t h2u(__half2 h) {
    return *reinterpret_cast<uint32_t*>(&h);
}

// ---------------------------------------------------------------------------
// 1) x fp32 -> fp16 (8 elems/thread)
// ---------------------------------------------------------------------------
__global__ void convert_x_kernel(const float* __restrict__ x) {
    size_t i = ((size_t)blockIdx.x * blockDim.x + threadIdx.x) * 8;
    float4 v0 = *reinterpret_cast<const float4*>(x + i);
    float4 v1 = *reinterpret_cast<const float4*>(x + i + 4);
    union { __half2 h[4]; uint4 u; } r;
    r.h[0] = __floats2half2_rn(v0.x, v0.y);
    r.h[1] = __floats2half2_rn(v0.z, v0.w);
    r.h[2] = __floats2half2_rn(v1.x, v1.y);
    r.h[3] = __floats2half2_rn(v1.z, v1.w);
    *reinterpret_cast<uint4*>(g_A + i) = r.u;
}

// ---------------------------------------------------------------------------
// 2) fused GEMM: out = x_fp16 * dequant(qweight) + bias
//    BM=128 BN=128 BK=64, A via 3-stage cp.async, B dequantized in-kernel
//    (int4 LDG -> fp16 magic-bias dequant -> swizzled STS), 112KB -> 2 CTAs/SM
// ---------------------------------------------------------------------------
#define BM 128
#define BN 128
#define BK 64
#define STAGES 3
#define A_BYTES (BM * BK * 2)               // 16 KB, 128 rows x 128B
#define B_BYTES (BK * BN * 2)               // 16 KB, 64 rows x 256B
#define STAGE_BYTES (A_BYTES + B_BYTES)     // 32 KB
#define TAB_OFF (STAGES * STAGE_BYTES)      // 96 KB
#define SMEM_BYTES (TAB_OFF + 16384)        // 112 KB -> 2 CTAs/SM
#define KITERS (KK / BK)                    // 64

#define SWZA(r, c) ((uint32_t)((r) * 128 + ((((c) ^ ((r) & 7))) << 4)))

__global__ void __launch_bounds__(256, 2)
gemm_kernel(const int* __restrict__ qw, const int* __restrict__ qz,
            const float* __restrict__ sc, const float* __restrict__ bias,
            float* __restrict__ out) {
    extern __shared__ char smem[];
    const uint32_t sb = smem_u32(smem);
    __half2* s2_tab = reinterpret_cast<__half2*>(smem + TAB_OFF);          // [32][64]
    __half2* z2_tab = reinterpret_cast<__half2*>(smem + TAB_OFF + 8192);   // [32][64]
    const int tid = threadIdx.x;
    const int wid = tid >> 5;
    const int lane = tid & 31;
    const int m0 = blockIdx.x * BM;         // 32 m-tiles (fast: share W in L2)
    const int n0 = blockIdx.y * BN;         // 86 n-tiles
    const int wm = wid & 1;                 // 0..1 (64 rows)
    const int wn = wid >> 1;                // 0..3 (32 cols)

    // ---- build per-CTA scale/zero tables: cols [n0, n0+128), 32 groups ----
    for (int idx = tid; idx < 2048; idx += 256) {
        int g = idx >> 6, np = idx & 63;
        int n = n0 + 2 * np;
        float s0 = sc[g * NN + n], s1 = sc[g * NN + n + 1];
        unsigned zw = (unsigned)qz[g * (NN / 8) + (n >> 3)];
        int sh = (n & 7) * 4;
        float z0 = (float)(1025 + (int)((zw >> sh) & 0xFu));
        float z1 = (float)(1025 + (int)((zw >> (sh + 4)) & 0xFu));
        s2_tab[idx] = __floats2half2_rn(s0, s1);
        z2_tab[idx] = __floats2half2_rn(z0, z1);   // 1024 + (zraw+1), exact
    }
    __syncthreads();

    const __half* gA = g_A + (size_t)m0 * KK;

    auto load_stage_A = [&](int s, int kc) {
        uint32_t sA = sb + s * STAGE_BYTES;
        const char* a = (const char*)(gA + kc * BK);
#pragma unroll
        for (int j = 0; j < 4; j++) {       // A: 1024 x 16B (128 rows x 128B)
            int q = j * 256 + tid;
            int r = q >> 3, c = q & 7;
            cp16(sA + SWZA(r, c), a + (size_t)r * (KK * 2) + c * 16);
        }
    };

    auto ldg_q = [&](int kc) -> uint4 {     // 8 k-rows x 4 n-cols of int4 nibbles
        return *reinterpret_cast<const uint4*>(
            qw + (size_t)(kc * 8 + wid) * NN + n0 + lane * 4);
    };

    // dequant q (chunk kc) and store into stage s's B region
    auto sts_b = [&](int s, int kc, uint4 q) {
        int g6 = (kc >> 1) * 64 + lane * 2;
        __half2 s01 = s2_tab[g6],     s23 = s2_tab[g6 + 1];
        __half2 z01 = z2_tab[g6],     z23 = z2_tab[g6 + 1];
        uint32_t base = sb + (uint32_t)s * STAGE_BYTES + A_BYTES
                      + (uint32_t)(wid * 2048) + (uint32_t)((lane & 1) * 8);
        uint32_t cpart = (uint32_t)(lane >> 1);
#pragma unroll
        for (int j = 0; j < 8; j++) {       // k row = wid*8 + j
            uint32_t t0 = ((q.x >> (4 * j)) & 0xFu) | 0x6400u;
            uint32_t t1 = ((q.y >> (4 * j)) & 0xFu) | 0x6400u;
            uint32_t t2 = ((q.z >> (4 * j)) & 0xFu) | 0x6400u;
            uint32_t t3 = ((q.w >> (4 * j)) & 0xFu) | 0x6400u;
            __half2 v01 = __hmul2(__hsub2(u2h(t0 | (t1 << 16)), z01), s01);
            __half2 v23 = __hmul2(__hsub2(u2h(t2 | (t3 << 16)), z23), s23);
            uint32_t addr = base + (uint32_t)(j * 256)
                          + ((cpart ^ (uint32_t)j) << 4);
            asm volatile("st.shared.v2.u32 [%0], {%1, %2};"
                         :: "r"(addr), "r"(h2u(v01)), "r"(h2u(v23)) : "memory");
        }
    };

    // precomputed LDSM addresses (validated R10/R12)
    const int x  = lane & 7;
    const int h  = lane >> 4;
    const int xk = x >> 1;
    const int xb = (x & 1) ^ h;
    uint32_t aBase[4];
#pragma unroll
    for (int mi = 0; mi < 4; mi++)
        aBase[mi] = (uint32_t)((wm * 64 + mi * 16 + (lane & 15)) * 128 + 16 * xb);
    uint32_t kso[4];
#pragma unroll
    for (int ks = 0; ks < 4; ks++) kso[ks] = (uint32_t)(32 * (ks ^ xk));
    uint32_t bBase[2];
#pragma unroll
    for (int nb = 0; nb < 2; nb++) {
        int c = wn * 4 + nb * 2 + h;
        bBase[nb] = (uint32_t)((lane & 15) * 256 + ((c ^ x) << 4));
    }

    // prologue
    uint4 qtmp = ldg_q(0);
    load_stage_A(0, 0);
    asm volatile("cp.async.commit_group;" ::: "memory");
    load_stage_A(1, 1);
    asm volatile("cp.async.commit_group;" ::: "memory");
    sts_b(0, 0, qtmp);
    uint4 qreg = ldg_q(1);

    float acc[4][4][4];
#pragma unroll
    for (int i = 0; i < 4; i++)
#pragma unroll
        for (int j = 0; j < 4; j++)
#pragma unroll
            for (int e = 0; e < 4; e++) acc[i][j][e] = 0.f;

    for (int it = 0; it < KITERS; it++) {
        asm volatile("cp.async.wait_group 1;" ::: "memory");
        __syncthreads();                    // A(it) + B(it) visible

        const int s = it % 3;
        if (it + 1 < KITERS) sts_b((it + 1) % 3, it + 1, qreg);
        if (it + 2 < KITERS) {
            qreg = ldg_q(it + 2);
            load_stage_A((it + 2) % 3, it + 2);
        }
        asm volatile("cp.async.commit_group;" ::: "memory");

        const uint32_t sA = sb + s * STAGE_BYTES;
        const uint32_t sB = sA + A_BYTES;
#pragma unroll
        for (int ks = 0; ks < 4; ks++) {
            uint32_t a[4][4];
#pragma unroll
            for (int mi = 0; mi < 4; mi++)
                ldsm4(a[mi][0], a[mi][1], a[mi][2], a[mi][3],
                      sA + aBase[mi] + kso[ks]);
            uint32_t b[2][4];
#pragma unroll
            for (int nb = 0; nb < 2; nb++)
                ldsm4t(b[nb][0], b[nb][1], b[nb][2], b[nb][3],
                       sB + (uint32_t)(ks * 4096) + bBase[nb]);
#pragma unroll
            for (int mi = 0; mi < 4; mi++)
#pragma unroll
                for (int ni = 0; ni < 4; ni++)
                    mma16816(acc[mi][ni], a[mi],
                             b[ni >> 1][(ni & 1) * 2], b[ni >> 1][(ni & 1) * 2 + 1]);
        }
    }

    // epilogue
#pragma unroll
    for (int mi = 0; mi < 4; mi++) {
        int r = m0 + wm * 64 + mi * 16 + (lane >> 2);
#pragma unroll
        for (int ni = 0; ni < 4; ni++) {
            int col = n0 + wn * 32 + ni * 8 + 2 * (lane & 3);
            float b0 = bias[col], b1 = bias[col + 1];
            float2 v0 = make_float2(acc[mi][ni][0] + b0, acc[mi][ni][1] + b1);
            float2 v1 = make_float2(acc[mi][ni][2] + b0, acc[mi][ni][3] + b1);
            *reinterpret_cast<float2*>(out + (size_t)r * NN + col) = v0;
            *reinterpret_cast<float2*>(out + (size_t)(r + 8) * NN + col) = v1;
        }
    }
}

// ---------------------------------------------------------------------------
// launch
// ---------------------------------------------------------------------------
extern "C" void kernel_launch(void* const* d_in, const int* in_sizes, int n_in,
                              void* d_out, int out_size) {
    const float* x    = (const float*)d_in[0];
    const int*   qw   = (const int*)d_in[1];
    const int*   qz   = (const int*)d_in[2];
    const float* sc   = (const float*)d_in[3];
    // d_in[4] = g_idx (k/128 by construction; unused)
    const float* bias = (const float*)d_in[5];
    float* out = (float*)d_out;

    cudaFuncSetAttribute(gemm_kernel, cudaFuncAttributeMaxDynamicSharedMemorySize,
                         SMEM_BYTES);

    convert_x_kernel<<<8192, 256>>>(x);             // 16.78M elems / 8 per thread
    gemm_kernel<<<dim3(MM / BM, NN / BN), 256, SMEM_BYTES>>>(qw, qz, sc, bias, out);
}

// round 16
// speedup vs baseline: 1.1406x; 1.1406x over previous
#include <cuda_runtime.h>
#include <cuda_fp16.h>
#include <cstdint>

#define KK 4096
#define NN 11008
#define MM 4096

// scratch
__device__ __half g_A[(size_t)MM * KK];   // x in fp16, [M, K]
__device__ __half g_W[(size_t)KK * NN];   // dequantized W in fp16, [K, N]

// ---------------------------------------------------------------------------
// helpers
// ---------------------------------------------------------------------------
__device__ __forceinline__ uint32_t smem_u32(const void* p) {
    uint32_t a;
    asm("{ .reg .u64 t; cvta.to.shared.u64 t, %1; cvt.u32.u64 %0, t; }"
        : "=r"(a) : "l"(p));
    return a;
}
__device__ __forceinline__ void cp16(uint32_t s, const void* g) {
    asm volatile("cp.async.cg.shared.global [%0], [%1], 16;" :: "r"(s), "l"(g));
}
__device__ __forceinline__ void ldsm4(uint32_t& r0, uint32_t& r1, uint32_t& r2,
                                      uint32_t& r3, uint32_t a) {
    asm volatile("ldmatrix.sync.aligned.m8n8.x4.shared.b16 {%0,%1,%2,%3}, [%4];"
                 : "=r"(r0), "=r"(r1), "=r"(r2), "=r"(r3) : "r"(a));
}
__device__ __forceinline__ void ldsm4t(uint32_t& r0, uint32_t& r1, uint32_t& r2,
                                       uint32_t& r3, uint32_t a) {
    asm volatile("ldmatrix.sync.aligned.m8n8.x4.trans.shared.b16 {%0,%1,%2,%3}, [%4];"
                 : "=r"(r0), "=r"(r1), "=r"(r2), "=r"(r3) : "r"(a));
}
__device__ __forceinline__ void mma16816(float* d, const uint32_t* a,
                                         uint32_t b0, uint32_t b1) {
    asm volatile("mma.sync.aligned.m16n8k16.row.col.f32.f16.f16.f32 "
                 "{%0,%1,%2,%3}, {%4,%5,%6,%7}, {%8,%9}, {%0,%1,%2,%3};"
                 : "+f"(d[0]), "+f"(d[1]), "+f"(d[2]), "+f"(d[3])
                 : "r"(a[0]), "r"(a[1]), "r"(a[2]), "r"(a[3]), "r"(b0), "r"(b1));
}

// ---------------------------------------------------------------------------
// 1) x fp32 -> fp16  (8 elems/thread)
// ---------------------------------------------------------------------------
__global__ void convert_x_kernel(const float* __restrict__ x) {
    size_t i = ((size_t)blockIdx.x * blockDim.x + threadIdx.x) * 8;
    float4 v0 = *reinterpret_cast<const float4*>(x + i);
    float4 v1 = *reinterpret_cast<const float4*>(x + i + 4);
    union { __half2 h[4]; uint4 u; } r;
    r.h[0] = __floats2half2_rn(v0.x, v0.y);
    r.h[1] = __floats2half2_rn(v0.z, v0.w);
    r.h[2] = __floats2half2_rn(v1.x, v1.y);
    r.h[3] = __floats2half2_rn(v1.z, v1.w);
    *reinterpret_cast<uint4*>(g_A + i) = r.u;
}

// ---------------------------------------------------------------------------
// 2) dequant int4 -> fp16 W [K, N]
// ---------------------------------------------------------------------------
__global__ void dequant_kernel(const int* __restrict__ qw,
                               const int* __restrict__ qz,
                               const float* __restrict__ sc) {
    int idx = blockIdx.x * blockDim.x + threadIdx.x;   // 4096 * 1376 threads
    int k  = idx / (NN / 8);
    int n8 = idx - k * (NN / 8);
    int n0 = n8 * 8;
    int g  = k >> 7;
    unsigned zw = (unsigned)qz[g * (NN / 8) + n8];
    int shift = (k & 7) * 4;
    const int*   qrow = qw + (size_t)(k >> 3) * NN + n0;
    const float* srow = sc + (size_t)g * NN + n0;
    union { __half h[8]; uint4 v; } r;
#pragma unroll
    for (int j = 0; j < 8; j++) {
        int q = ((unsigned)qrow[j] >> shift) & 0xF;
        int z = (int)((zw >> (4 * j)) & 0xFu) + 1;
        r.h[j] = __float2half_rn((float)(q - z) * srow[j]);
    }
    *reinterpret_cast<uint4*>(g_W + (size_t)k * NN + n0) = r.v;
}

// ---------------------------------------------------------------------------
// 3) HMMA GEMM (R14 champion + 3x-unrolled k-loop: compile-time stage index)
//    BM=128 BN=128 BK=64, 3-stage cp.async, 96KB -> 2 CTAs/SM,
//    8 warps as 2m x 4n (warp 64x32), register double-buffered fragments
// ---------------------------------------------------------------------------
#define BM 128
#define BN 128
#define BK 64
#define STAGES 3
#define A_BYTES (BM * BK * 2)              // 16 KB, 128 rows x 128B
#define B_BYTES (BK * BN * 2)              // 16 KB, 64 rows x 256B
#define STAGE_BYTES (A_BYTES + B_BYTES)    // 32 KB
#define SMEM_BYTES (STAGES * STAGE_BYTES)  // 96 KB -> 2 CTAs/SM
#define KITERS (KK / BK)                   // 64

#define SWZA(r, c) ((uint32_t)((r) * 128 + ((((c) ^ ((r) & 7))) << 4)))
#define SWZB(r, c) ((uint32_t)((r) * 256 + ((((c) ^ ((r) & 7))) << 4)))

__global__ void __launch_bounds__(256, 2)
gemm_kernel(const float* __restrict__ bias, float* __restrict__ out) {
    extern __shared__ char smem[];
    const uint32_t sb = smem_u32(smem);
    const int tid = threadIdx.x;
    const int wid = tid >> 5;
    const int lane = tid & 31;
    const int m0 = blockIdx.x * BM;        // 32 m-tiles (fast: share W in L2)
    const int n0 = blockIdx.y * BN;        // 86 n-tiles
    const int wm = wid & 1;                // 0..1 (64 rows)
    const int wn = wid >> 1;               // 0..3 (32 cols)

    const __half* gA = g_A + (size_t)m0 * KK;
    const __half* gW = g_W + n0;

    auto load_stage = [&](int s, int kc) {
        uint32_t sA = sb + s * STAGE_BYTES;
        uint32_t sB = sA + A_BYTES;
        const char* a = (const char*)(gA + kc * BK);
        const char* b = (const char*)(gW + (size_t)(kc * BK) * NN);
#pragma unroll
        for (int j = 0; j < 4; j++) {      // A: 1024 x 16B (128 rows x 128B)
            int q = j * 256 + tid;
            int r = q >> 3, c = q & 7;
            cp16(sA + SWZA(r, c), a + (size_t)r * (KK * 2) + c * 16);
        }
#pragma unroll
        for (int j = 0; j < 4; j++) {      // B: 1024 x 16B (64 rows x 256B)
            int q = j * 256 + tid;
            int r = q >> 4, c = q & 15;
            cp16(sB + SWZB(r, c), b + (size_t)r * (NN * 2) + c * 16);
        }
    };

    // per-warp fragment double buffers
    uint32_t a_frag[2][4][4];
    uint32_t b_frag[2][2][4];

    auto load_frags = [&](uint32_t sA, uint32_t sB, int ks, int buf) {
#pragma unroll
        for (int mi = 0; mi < 4; mi++) {
            int r = wm * 64 + mi * 16 + (lane & 15);
            int c = 2 * ks + (lane >> 4);
            ldsm4(a_frag[buf][mi][0], a_frag[buf][mi][1],
                  a_frag[buf][mi][2], a_frag[buf][mi][3], sA + SWZA(r, c));
        }
#pragma unroll
        for (int nb = 0; nb < 2; nb++) {
            int r = ks * 16 + (lane & 7) + ((lane >> 3) & 1) * 8;
            int c = wn * 4 + nb * 2 + (lane >> 4);
            ldsm4t(b_frag[buf][nb][0], b_frag[buf][nb][1],
                   b_frag[buf][nb][2], b_frag[buf][nb][3], sB + SWZB(r, c));
        }
    };

    float acc[4][4][4];
#pragma unroll
    for (int i = 0; i < 4; i++)
#pragma unroll
        for (int j = 0; j < 4; j++)
#pragma unroll
            for (int e = 0; e < 4; e++) acc[i][j][e] = 0.f;

    // one k-chunk body with compile-time stage constant
    auto body = [&](int S, int it) {
        asm volatile("cp.async.wait_group 1;" ::: "memory");
        __syncthreads();
        if (it + 2 < KITERS) {
            int ls = S + 2 >= STAGES ? S + 2 - STAGES : S + 2;
            load_stage(ls, it + 2);
        }
        asm volatile("cp.async.commit_group;" ::: "memory");

        const uint32_t sA = sb + (uint32_t)(S * STAGE_BYTES);
        const uint32_t sB = sA + A_BYTES;
        load_frags(sA, sB, 0, 0);
#pragma unroll
        for (int ks = 0; ks < 4; ks++) {
            int cur = ks & 1;
            if (ks < 3) load_frags(sA, sB, ks + 1, cur ^ 1);
#pragma unroll
            for (int mi = 0; mi < 4; mi++)
#pragma unroll
                for (int ni = 0; ni < 4; ni++)
                    mma16816(acc[mi][ni], a_frag[cur][mi],
                             b_frag[cur][ni >> 1][(ni & 1) * 2],
                             b_frag[cur][ni >> 1][(ni & 1) * 2 + 1]);
        }
    };

    // prologue: 2 stages in flight
    load_stage(0, 0);
    asm volatile("cp.async.commit_group;" ::: "memory");
    load_stage(1, 1);
    asm volatile("cp.async.commit_group;" ::: "memory");

    // 63 = 21 x 3 unrolled (stage index compile-time), then tail chunk 63
    for (int it = 0; it < 63; it += 3) {
        body(0, it);
        body(1, it + 1);
        body(2, it + 2);
    }
    body(0, 63);

    // epilogue
#pragma unroll
    for (int mi = 0; mi < 4; mi++) {
        int r = m0 + wm * 64 + mi * 16 + (lane >> 2);
#pragma unroll
        for (int ni = 0; ni < 4; ni++) {
            int col = n0 + wn * 32 + ni * 8 + 2 * (lane & 3);
            float b0 = bias[col], b1 = bias[col + 1];
            float2 v0 = make_float2(acc[mi][ni][0] + b0, acc[mi][ni][1] + b1);
            float2 v1 = make_float2(acc[mi][ni][2] + b0, acc[mi][ni][3] + b1);
            *reinterpret_cast<float2*>(out + (size_t)r * NN + col) = v0;
            *reinterpret_cast<float2*>(out + (size_t)(r + 8) * NN + col) = v1;
        }
    }
}

// ---------------------------------------------------------------------------
// launch
// ---------------------------------------------------------------------------
extern "C" void kernel_launch(void* const* d_in, const int* in_sizes, int n_in,
                              void* d_out, int out_size) {
    const float* x    = (const float*)d_in[0];
    const int*   qw   = (const int*)d_in[1];
    const int*   qz   = (const int*)d_in[2];
    const float* sc   = (const float*)d_in[3];
    // d_in[4] = g_idx (k/128 by construction; unused)
    const float* bias = (const float*)d_in[5];
    float* out = (float*)d_out;

    cudaFuncSetAttribute(gemm_kernel, cudaFuncAttributeMaxDynamicSharedMemorySize,
                         SMEM_BYTES);

    convert_x_kernel<<<8192, 256>>>(x);             // 16.78M elems / 8 per thread
    dequant_kernel<<<22016, 256>>>(qw, qz, sc);     // 4096 * 1376 threads
    gemm_kernel<<<dim3(MM / BM, NN / BN), 256, SMEM_BYTES>>>(bias, out);
}

// round 17
// speedup vs baseline: 1.1754x; 1.0306x over previous
#include <cuda_runtime.h>
#include <cuda_fp16.h>
#include <cstdint>

#define KK 4096
#define NN 11008
#define MM 4096

// scratch
__device__ __half g_A[(size_t)MM * KK];   // x in fp16, [M, K]
__device__ __half g_W[(size_t)KK * NN];   // dequantized W in fp16, [K, N]

// ---------------------------------------------------------------------------
// helpers
// ---------------------------------------------------------------------------
__device__ __forceinline__ uint32_t smem_u32(const void* p) {
    uint32_t a;
    asm("{ .reg .u64 t; cvta.to.shared.u64 t, %1; cvt.u32.u64 %0, t; }"
        : "=r"(a) : "l"(p));
    return a;
}
__device__ __forceinline__ void cp16(uint32_t s, const void* g) {
    asm volatile("cp.async.cg.shared.global [%0], [%1], 16;" :: "r"(s), "l"(g));
}
__device__ __forceinline__ void ldsm4(uint32_t& r0, uint32_t& r1, uint32_t& r2,
                                      uint32_t& r3, uint32_t a) {
    asm volatile("ldmatrix.sync.aligned.m8n8.x4.shared.b16 {%0,%1,%2,%3}, [%4];"
                 : "=r"(r0), "=r"(r1), "=r"(r2), "=r"(r3) : "r"(a));
}
__device__ __forceinline__ void ldsm4t(uint32_t& r0, uint32_t& r1, uint32_t& r2,
                                       uint32_t& r3, uint32_t a) {
    asm volatile("ldmatrix.sync.aligned.m8n8.x4.trans.shared.b16 {%0,%1,%2,%3}, [%4];"
                 : "=r"(r0), "=r"(r1), "=r"(r2), "=r"(r3) : "r"(a));
}
__device__ __forceinline__ void mma16816(float* d, const uint32_t* a,
                                         uint32_t b0, uint32_t b1) {
    asm volatile("mma.sync.aligned.m16n8k16.row.col.f32.f16.f16.f32 "
                 "{%0,%1,%2,%3}, {%4,%5,%6,%7}, {%8,%9}, {%0,%1,%2,%3};"
                 : "+f"(d[0]), "+f"(d[1]), "+f"(d[2]), "+f"(d[3])
                 : "r"(a[0]), "r"(a[1]), "r"(a[2]), "r"(a[3]), "r"(b0), "r"(b1));
}

// ---------------------------------------------------------------------------
// 1) x fp32 -> fp16  (8 elems/thread)
// ---------------------------------------------------------------------------
__global__ void convert_x_kernel(const float* __restrict__ x) {
    size_t i = ((size_t)blockIdx.x * blockDim.x + threadIdx.x) * 8;
    float4 v0 = *reinterpret_cast<const float4*>(x + i);
    float4 v1 = *reinterpret_cast<const float4*>(x + i + 4);
    union { __half2 h[4]; uint4 u; } r;
    r.h[0] = __floats2half2_rn(v0.x, v0.y);
    r.h[1] = __floats2half2_rn(v0.z, v0.w);
    r.h[2] = __floats2half2_rn(v1.x, v1.y);
    r.h[3] = __floats2half2_rn(v1.z, v1.w);
    *reinterpret_cast<uint4*>(g_A + i) = r.u;
}

// ---------------------------------------------------------------------------
// 2) dequant int4 -> fp16 W [K, N]
// ---------------------------------------------------------------------------
__global__ void dequant_kernel(const int* __restrict__ qw,
                               const int* __restrict__ qz,
                               const float* __restrict__ sc) {
    int idx = blockIdx.x * blockDim.x + threadIdx.x;   // 4096 * 1376 threads
    int k  = idx / (NN / 8);
    int n8 = idx - k * (NN / 8);
    int n0 = n8 * 8;
    int g  = k >> 7;
    unsigned zw = (unsigned)qz[g * (NN / 8) + n8];
    int shift = (k & 7) * 4;
    const int*   qrow = qw + (size_t)(k >> 3) * NN + n0;
    const float* srow = sc + (size_t)g * NN + n0;
    union { __half h[8]; uint4 v; } r;
#pragma unroll
    for (int j = 0; j < 8; j++) {
        int q = ((unsigned)qrow[j] >> shift) & 0xF;
        int z = (int)((zw >> (4 * j)) & 0xFu) + 1;
        r.h[j] = __float2half_rn((float)(q - z) * srow[j]);
    }
    *reinterpret_cast<uint4*>(g_W + (size_t)k * NN + n0) = r.v;
}

// ---------------------------------------------------------------------------
// 3) HMMA GEMM (R16 champion + rolling pointers + peeled drain)
//    BM=128 BN=128 BK=64, 3-stage cp.async, 96KB -> 2 CTAs/SM,
//    8 warps as 2m x 4n (warp 64x32), register double-buffered fragments
// ---------------------------------------------------------------------------
#define BM 128
#define BN 128
#define BK 64
#define STAGES 3
#define A_BYTES (BM * BK * 2)              // 16 KB, 128 rows x 128B
#define B_BYTES (BK * BN * 2)              // 16 KB, 64 rows x 256B
#define STAGE_BYTES (A_BYTES + B_BYTES)    // 32 KB
#define SMEM_BYTES (STAGES * STAGE_BYTES)  // 96 KB -> 2 CTAs/SM
#define KITERS (KK / BK)                   // 64

#define SWZA(r, c) ((uint32_t)((r) * 128 + ((((c) ^ ((r) & 7))) << 4)))
#define SWZB(r, c) ((uint32_t)((r) * 256 + ((((c) ^ ((r) & 7))) << 4)))

__global__ void __launch_bounds__(256, 2)
gemm_kernel(const float* __restrict__ bias, float* __restrict__ out) {
    extern __shared__ char smem[];
    const uint32_t sb = smem_u32(smem);
    const int tid = threadIdx.x;
    const int wid = tid >> 5;
    const int lane = tid & 31;
    const int m0 = blockIdx.x * BM;        // 32 m-tiles (fast: share W in L2)
    const int n0 = blockIdx.y * BN;        // 86 n-tiles
    const int wm = wid & 1;                // 0..1 (64 rows)
    const int wn = wid >> 1;               // 0..3 (32 cols)

    // rolling global pointers: per-thread base of this thread's cp.async slot
    int qa = tid;                           // A row/chunk assignment
    const char* aPtr = (const char*)(g_A + (size_t)m0 * KK)
                     + (size_t)(qa >> 3) * (KK * 2) + (qa & 7) * 16;
    const char* bPtr = (const char*)(g_W + n0)
                     + (size_t)(qa >> 4) * (NN * 2) + (qa & 15) * 16;
    // per-thread fixed smem offsets for the 4 A rows / 4 B rows it fills
    uint32_t aOff[4], bOff[4];
#pragma unroll
    for (int j = 0; j < 4; j++) {
        int q = j * 256 + tid;
        aOff[j] = SWZA(q >> 3, q & 7);
        q = j * 256 + tid;
        bOff[j] = SWZB(q >> 4, q & 15);
    }

    auto load_stage = [&]() {               // loads "next" chunk, advances ptrs
        uint32_t sA = 0, sB = 0;            // caller adds stage base
        (void)sA; (void)sB;
    };
    (void)load_stage;

    auto load_into = [&](uint32_t stage_base) {
        uint32_t sA = stage_base;
        uint32_t sB = stage_base + A_BYTES;
#pragma unroll
        for (int j = 0; j < 4; j++)          // A: 4 rows x 16B, row stride 32 rows
            cp16(sA + aOff[j], aPtr + (size_t)(j * 32) * (KK * 2));
#pragma unroll
        for (int j = 0; j < 4; j++)          // B: 4 rows x 16B, row stride 16 rows
            cp16(sB + bOff[j], bPtr + (size_t)(j * 16) * (NN * 2));
        aPtr += BK * 2;                      // next k chunk
        bPtr += (size_t)BK * NN * 2;
    };

    // per-warp fragment double buffers
    uint32_t a_frag[2][4][4];
    uint32_t b_frag[2][2][4];

    auto load_frags = [&](uint32_t sA, uint32_t sB, int ks, int buf) {
#pragma unroll
        for (int mi = 0; mi < 4; mi++) {
            int r = wm * 64 + mi * 16 + (lane & 15);
            int c = 2 * ks + (lane >> 4);
            ldsm4(a_frag[buf][mi][0], a_frag[buf][mi][1],
                  a_frag[buf][mi][2], a_frag[buf][mi][3], sA + SWZA(r, c));
        }
#pragma unroll
        for (int nb = 0; nb < 2; nb++) {
            int r = ks * 16 + (lane & 7) + ((lane >> 3) & 1) * 8;
            int c = wn * 4 + nb * 2 + (lane >> 4);
            ldsm4t(b_frag[buf][nb][0], b_frag[buf][nb][1],
                   b_frag[buf][nb][2], b_frag[buf][nb][3], sB + SWZB(r, c));
        }
    };

    float acc[4][4][4];
#pragma unroll
    for (int i = 0; i < 4; i++)
#pragma unroll
        for (int j = 0; j < 4; j++)
#pragma unroll
            for (int e = 0; e < 4; e++) acc[i][j][e] = 0.f;

    // one k-chunk body; S and PRE are compile-time at every call site
    auto body = [&](int S, bool PRE) {
        asm volatile("cp.async.wait_group 1;" ::: "memory");
        __syncthreads();
        if (PRE) {
            int ls = S + 2 >= STAGES ? S + 2 - STAGES : S + 2;
            load_into(sb + (uint32_t)(ls * STAGE_BYTES));
        }
        asm volatile("cp.async.commit_group;" ::: "memory");

        const uint32_t sA = sb + (uint32_t)(S * STAGE_BYTES);
        const uint32_t sB = sA + A_BYTES;
        load_frags(sA, sB, 0, 0);
#pragma unroll
        for (int ks = 0; ks < 4; ks++) {
            int cur = ks & 1;
            if (ks < 3) load_frags(sA, sB, ks + 1, cur ^ 1);
#pragma unroll
            for (int mi = 0; mi < 4; mi++)
#pragma unroll
                for (int ni = 0; ni < 4; ni++)
                    mma16816(acc[mi][ni], a_frag[cur][mi],
                             b_frag[cur][ni >> 1][(ni & 1) * 2],
                             b_frag[cur][ni >> 1][(ni & 1) * 2 + 1]);
        }
    };

    // prologue: 2 stages in flight
    load_into(sb);
    asm volatile("cp.async.commit_group;" ::: "memory");
    load_into(sb + STAGE_BYTES);
    asm volatile("cp.async.commit_group;" ::: "memory");

    // 64 chunks = 20x3 hot bodies (branch-free) + 4 peeled drain bodies
#pragma unroll 1
    for (int it = 0; it < 60; it += 3) {
        body(0, true);
        body(1, true);
        body(2, true);
    }
    body(0, true);     // it=60, loads 62
    body(1, true);     // it=61, loads 63
    body(2, false);    // it=62
    body(0, false);    // it=63

    // epilogue
#pragma unroll
    for (int mi = 0; mi < 4; mi++) {
        int r = m0 + wm * 64 + mi * 16 + (lane >> 2);
        float* orow = out + (size_t)r * NN;
#pragma unroll
        for (int ni = 0; ni < 4; ni++) {
            int col = n0 + wn * 32 + ni * 8 + 2 * (lane & 3);
            float b0 = __ldg(bias + col), b1 = __ldg(bias + col + 1);
            float2 v0 = make_float2(acc[mi][ni][0] + b0, acc[mi][ni][1] + b1);
            float2 v1 = make_float2(acc[mi][ni][2] + b0, acc[mi][ni][3] + b1);
            *reinterpret_cast<float2*>(orow + col) = v0;
            *reinterpret_cast<float2*>(orow + NN * 8 + col) = v1;
        }
    }
}

// ---------------------------------------------------------------------------
// launch
// ---------------------------------------------------------------------------
extern "C" void kernel_launch(void* const* d_in, const int* in_sizes, int n_in,
                              void* d_out, int out_size) {
    const float* x    = (const float*)d_in[0];
    const int*   qw   = (const int*)d_in[1];
    const int*   qz   = (const int*)d_in[2];
    const float* sc   = (const float*)d_in[3];
    // d_in[4] = g_idx (k/128 by construction; unused)
    const float* bias = (const float*)d_in[5];
    float* out = (float*)d_out;

    cudaFuncSetAttribute(gemm_kernel, cudaFuncAttributeMaxDynamicSharedMemorySize,
                         SMEM_BYTES);

    convert_x_kernel<<<8192, 256>>>(x);             // 16.78M elems / 8 per thread
    dequant_kernel<<<22016, 256>>>(qw, qz, sc);     // 4096 * 1376 threads
    gemm_kernel<<<dim3(MM / BM, NN / BN), 256, SMEM_BYTES>>>(bias, out);
}